// round 1
// baseline (speedup 1.0000x reference)
#include <cuda_runtime.h>
#include <cuda_bf16.h>

// Problem shapes (fixed by the dataset)
#define BATCH 64
#define SEQ   4096
#define DIM   256
#define LN_EPS 1e-3f

#define NBPB   8                      // blocks per batch
#define WARPS  8                      // warps per block
#define NSPLIT (NBPB * WARPS)         // 64 splits per batch
#define ROWS   (SEQ / NSPLIT)         // 64 rows per warp

// Scratch for split-softmax partials (no cudaMalloc allowed)
__device__ float g_pm[BATCH * NSPLIT];
__device__ float g_pz[BATCH * NSPLIT];
__device__ float g_pacc[(size_t)BATCH * NSPLIT * DIM];

// ---------------------------------------------------------------------------
// Stage 1: each warp owns a contiguous chunk of rows of one batch.
// Per row (in registers): LayerNorm stats + score, then online-softmax update
// of (m, Z, acc[DIM]).  x is read exactly once.
// ---------------------------------------------------------------------------
__global__ __launch_bounds__(256, 4)
void ap_stage1(const float* __restrict__ x,
               const float* __restrict__ mask,
               const float* __restrict__ gamma,
               const float* __restrict__ beta,
               const float* __restrict__ w,
               const float* __restrict__ bbias)
{
    __shared__ __align__(16) float s_gw[DIM];
    __shared__ float s_ra[WARPS], s_rc[WARPS];
    __shared__ float s_c1, s_c2;

    const int tid  = threadIdx.x;
    const int lane = tid & 31;
    const int wid  = tid >> 5;

    // gw[d] = gamma[d]*w[d];  c1 = sum gw;  c2 = sum beta*w + bias
    {
        float gwv = gamma[tid] * w[tid];
        float bwv = beta[tid]  * w[tid];
        s_gw[tid] = gwv;
        float a = gwv, c = bwv;
        #pragma unroll
        for (int o = 16; o; o >>= 1) {
            a += __shfl_xor_sync(0xFFFFFFFFu, a, o);
            c += __shfl_xor_sync(0xFFFFFFFFu, c, o);
        }
        if (lane == 0) { s_ra[wid] = a; s_rc[wid] = c; }
        __syncthreads();
        if (tid == 0) {
            float A = 0.f, C = 0.f;
            #pragma unroll
            for (int i = 0; i < WARPS; i++) { A += s_ra[i]; C += s_rc[i]; }
            s_c1 = A;
            s_c2 = C + bbias[0];
        }
        __syncthreads();
    }
    const float c1 = s_c1;
    const float c2 = s_c2;

    // Per-lane gw slice (two float4s from shared, fixed for the whole loop)
    const float4* gw4 = reinterpret_cast<const float4*>(s_gw);
    const float4 g0 = gw4[lane];
    const float4 g1 = gw4[32 + lane];

    const int b     = blockIdx.x / NBPB;
    const int split = (blockIdx.x % NBPB) * WARPS + wid;
    const int s0    = split * ROWS;

    const float4* xb   = reinterpret_cast<const float4*>(x + (size_t)b * SEQ * DIM);
    const float*  mrow = mask + (size_t)b * SEQ;

    float  m = -1e30f, Z = 0.f;
    float4 acc0 = make_float4(0.f, 0.f, 0.f, 0.f);
    float4 acc1 = make_float4(0.f, 0.f, 0.f, 0.f);

    for (int r = 0; r < ROWS; r++) {
        const int s = s0 + r;
        const float4* rp = xb + (size_t)s * (DIM / 4);
        const float4 v0 = rp[lane];
        const float4 v1 = rp[32 + lane];

        // Lane partials: sum x, sum x^2, dot(x, gw)
        float sx  = (v0.x + v0.y) + (v0.z + v0.w) + (v1.x + v1.y) + (v1.z + v1.w);
        float sxx = v0.x*v0.x + v0.y*v0.y + v0.z*v0.z + v0.w*v0.w
                  + v1.x*v1.x + v1.y*v1.y + v1.z*v1.z + v1.w*v1.w;
        float sgw = v0.x*g0.x + v0.y*g0.y + v0.z*g0.z + v0.w*g0.w
                  + v1.x*g1.x + v1.y*g1.y + v1.z*g1.z + v1.w*g1.w;

        #pragma unroll
        for (int o = 16; o; o >>= 1) {
            sx  += __shfl_xor_sync(0xFFFFFFFFu, sx,  o);
            sxx += __shfl_xor_sync(0xFFFFFFFFu, sxx, o);
            sgw += __shfl_xor_sync(0xFFFFFFFFu, sgw, o);
        }

        const float mu   = sx * (1.f / DIM);
        const float var  = sxx * (1.f / DIM) - mu * mu;
        const float rstd = rsqrtf(var + LN_EPS);
        float score = rstd * (sgw - mu * c1) + c2;
        score += (1.f - mrow[s]) * -1e9f;   // mask

        // Online softmax update
        const float mn = fmaxf(m, score);
        const float sc = __expf(m - mn);
        const float e  = __expf(score - mn);
        Z = Z * sc + e;
        acc0.x = acc0.x * sc + e * v0.x;
        acc0.y = acc0.y * sc + e * v0.y;
        acc0.z = acc0.z * sc + e * v0.z;
        acc0.w = acc0.w * sc + e * v0.w;
        acc1.x = acc1.x * sc + e * v1.x;
        acc1.y = acc1.y * sc + e * v1.y;
        acc1.z = acc1.z * sc + e * v1.z;
        acc1.w = acc1.w * sc + e * v1.w;
        m = mn;
    }

    // Write split partials
    float4* pa4 = reinterpret_cast<float4*>(g_pacc + ((size_t)b * NSPLIT + split) * DIM);
    pa4[lane]      = acc0;
    pa4[32 + lane] = acc1;
    if (lane == 0) {
        g_pm[b * NSPLIT + split] = m;
        g_pz[b * NSPLIT + split] = Z;
    }
}

// ---------------------------------------------------------------------------
// Stage 2: per batch, merge NSPLIT partial softmaxes -> out[b, d]
// ---------------------------------------------------------------------------
__global__ __launch_bounds__(256)
void ap_stage2(float* __restrict__ out)
{
    const int b   = blockIdx.x;
    const int tid = threadIdx.x;

    __shared__ float sm[NSPLIT], sz[NSPLIT], sscale[NSPLIT];
    __shared__ float s_invZ;

    if (tid < NSPLIT) {
        sm[tid] = g_pm[b * NSPLIT + tid];
        sz[tid] = g_pz[b * NSPLIT + tid];
    }
    __syncthreads();

    if (tid == 0) {
        float M = -1e30f;
        #pragma unroll 8
        for (int i = 0; i < NSPLIT; i++) M = fmaxf(M, sm[i]);
        float Zt = 0.f;
        for (int i = 0; i < NSPLIT; i++) {
            const float sc = __expf(sm[i] - M);
            sscale[i] = sc;
            Zt += sz[i] * sc;
        }
        s_invZ = 1.f / Zt;
    }
    __syncthreads();

    const float invZ = s_invZ;
    const float* pb = g_pacc + (size_t)b * NSPLIT * DIM;
    float a = 0.f;
    #pragma unroll 8
    for (int sdx = 0; sdx < NSPLIT; sdx++)
        a += sscale[sdx] * pb[sdx * DIM + tid];

    out[b * DIM + tid] = a * invZ;
}

// ---------------------------------------------------------------------------
extern "C" void kernel_launch(void* const* d_in, const int* in_sizes, int n_in,
                              void* d_out, int out_size)
{
    const float* x     = (const float*)d_in[0];
    const float* mask  = (const float*)d_in[1];
    const float* gamma = (const float*)d_in[2];
    const float* beta  = (const float*)d_in[3];
    const float* w     = (const float*)d_in[4];
    const float* bbias = (const float*)d_in[5];
    float* out = (float*)d_out;

    ap_stage1<<<BATCH * NBPB, 256>>>(x, mask, gamma, beta, w, bbias);
    ap_stage2<<<BATCH, 256>>>(out);
}

// round 2
// speedup vs baseline: 1.1744x; 1.1744x over previous
#include <cuda_runtime.h>
#include <cuda_bf16.h>

// Problem shapes (fixed by the dataset)
#define BATCH 64
#define SEQ   4096
#define DIM   256
#define LN_EPS 1e-3f

#define NBPB   8                      // blocks per batch
#define WARPS  8                      // warps per block
#define NSPLIT (NBPB * WARPS)         // 64 splits per batch
#define ROWS   (SEQ / NSPLIT)         // 64 rows per warp

// Scratch (no cudaMalloc allowed). Zero-initialized at module load;
// g_ticket is reset to 0 by the merging block each launch -> graph-replay safe.
__device__ float g_pm[BATCH * NSPLIT];
__device__ float g_pz[BATCH * NSPLIT];
__device__ float g_pacc[(size_t)BATCH * NSPLIT * DIM];
__device__ unsigned int g_ticket[BATCH];

// ---------------------------------------------------------------------------
// Single fused kernel:
//   phase A: each warp streams ROWS rows of one batch; per row computes
//            LN stats + score in registers and does an online-softmax update
//            with a fast path (no rescale) when the running max doesn't move.
//            Row r+1 is prefetched while row r is reduced (2x MLP).
//   phase B: the LAST block of each batch (atomic ticket) merges the NSPLIT
//            split-softmax partials and writes out[b, :].
// ---------------------------------------------------------------------------
__global__ __launch_bounds__(256, 4)
void ap_fused(const float* __restrict__ x,
              const float* __restrict__ mask,
              const float* __restrict__ gamma,
              const float* __restrict__ beta,
              const float* __restrict__ w,
              const float* __restrict__ bbias,
              float* __restrict__ out)
{
    __shared__ __align__(16) float s_gw[DIM];
    __shared__ float s_ra[WARPS], s_rc[WARPS];
    __shared__ float s_c1, s_c2;
    __shared__ int   s_last;
    __shared__ float s_scale[NSPLIT];
    __shared__ float s_invZ;

    const int tid  = threadIdx.x;
    const int lane = tid & 31;
    const int wid  = tid >> 5;

    // gw[d] = gamma[d]*w[d];  c1 = sum gw;  c2 = sum beta*w + bias
    {
        float gwv = gamma[tid] * w[tid];
        float bwv = beta[tid]  * w[tid];
        s_gw[tid] = gwv;
        float a = gwv, c = bwv;
        #pragma unroll
        for (int o = 16; o; o >>= 1) {
            a += __shfl_xor_sync(0xFFFFFFFFu, a, o);
            c += __shfl_xor_sync(0xFFFFFFFFu, c, o);
        }
        if (lane == 0) { s_ra[wid] = a; s_rc[wid] = c; }
        __syncthreads();
        if (tid == 0) {
            float A = 0.f, C = 0.f;
            #pragma unroll
            for (int i = 0; i < WARPS; i++) { A += s_ra[i]; C += s_rc[i]; }
            s_c1 = A;
            s_c2 = C + bbias[0];
        }
        __syncthreads();
    }
    const float c1 = s_c1;
    const float c2 = s_c2;

    const float4* gw4 = reinterpret_cast<const float4*>(s_gw);
    const float4 g0 = gw4[lane];
    const float4 g1 = gw4[32 + lane];

    const int b     = blockIdx.x / NBPB;
    const int split = (blockIdx.x % NBPB) * WARPS + wid;
    const int s0    = split * ROWS;

    const float4* xb   = reinterpret_cast<const float4*>(x + (size_t)b * SEQ * DIM);
    const float*  mrow = mask + (size_t)b * SEQ;

    float  m = -1e30f, Z = 0.f;
    float4 acc0 = make_float4(0.f, 0.f, 0.f, 0.f);
    float4 acc1 = make_float4(0.f, 0.f, 0.f, 0.f);

    // Prime the pipeline: row s0 in flight.
    const float4* rp = xb + (size_t)s0 * (DIM / 4);
    float4 v0 = rp[lane];
    float4 v1 = rp[32 + lane];
    float  mk = mrow[s0];

    for (int r = 0; r < ROWS; r++) {
        // Prefetch next row (clamped on last iter; loads always issue -> MLP=4 lines)
        const float4* np = rp + ((r + 1 < ROWS) ? (DIM / 4) : 0);
        const float4 n0 = np[lane];
        const float4 n1 = np[32 + lane];
        const float  mkn = mrow[s0 + ((r + 1 < ROWS) ? r + 1 : r)];

        // Lane partials: sum x, sum x^2, dot(x, gw)
        float sx  = (v0.x + v0.y) + (v0.z + v0.w) + (v1.x + v1.y) + (v1.z + v1.w);
        float sxx = v0.x*v0.x + v0.y*v0.y + v0.z*v0.z + v0.w*v0.w
                  + v1.x*v1.x + v1.y*v1.y + v1.z*v1.z + v1.w*v1.w;
        float sgw = v0.x*g0.x + v0.y*g0.y + v0.z*g0.z + v0.w*g0.w
                  + v1.x*g1.x + v1.y*g1.y + v1.z*g1.z + v1.w*g1.w;

        #pragma unroll
        for (int o = 16; o; o >>= 1) {
            sx  += __shfl_xor_sync(0xFFFFFFFFu, sx,  o);
            sxx += __shfl_xor_sync(0xFFFFFFFFu, sxx, o);
            sgw += __shfl_xor_sync(0xFFFFFFFFu, sgw, o);
        }

        const float mu   = sx * (1.f / DIM);
        const float var  = sxx * (1.f / DIM) - mu * mu;
        const float rstd = rsqrtf(var + LN_EPS);
        float score = rstd * (sgw - mu * c1) + c2;
        score += (1.f - mk) * -1e9f;   // mask

        // Online softmax; score is warp-uniform -> no divergence.
        if (score <= m) {
            // Fast path: max unchanged, no rescale (8 independent FMAs).
            const float e = __expf(score - m);
            Z += e;
            acc0.x += e * v0.x;  acc0.y += e * v0.y;
            acc0.z += e * v0.z;  acc0.w += e * v0.w;
            acc1.x += e * v1.x;  acc1.y += e * v1.y;
            acc1.z += e * v1.z;  acc1.w += e * v1.w;
        } else {
            // Rare path: new max; e == 1.
            const float sc = __expf(m - score);
            m = score;
            Z = fmaf(Z, sc, 1.f);
            acc0.x = fmaf(acc0.x, sc, v0.x);  acc0.y = fmaf(acc0.y, sc, v0.y);
            acc0.z = fmaf(acc0.z, sc, v0.z);  acc0.w = fmaf(acc0.w, sc, v0.w);
            acc1.x = fmaf(acc1.x, sc, v1.x);  acc1.y = fmaf(acc1.y, sc, v1.y);
            acc1.z = fmaf(acc1.z, sc, v1.z);  acc1.w = fmaf(acc1.w, sc, v1.w);
        }

        rp += (DIM / 4);
        v0 = n0; v1 = n1; mk = mkn;
    }

    // Write split partials
    float4* pa4 = reinterpret_cast<float4*>(g_pacc + ((size_t)b * NSPLIT + split) * DIM);
    pa4[lane]      = acc0;
    pa4[32 + lane] = acc1;
    if (lane == 0) {
        g_pm[b * NSPLIT + split] = m;
        g_pz[b * NSPLIT + split] = Z;
    }

    // ---- last-block-per-batch merge (threadfence reduction pattern) ----
    __threadfence();
    __syncthreads();
    if (tid == 0) {
        s_last = (atomicAdd(&g_ticket[b], 1u) == NBPB - 1);
        if (s_last) g_ticket[b] = 0;   // reset for next launch / graph replay
    }
    __syncthreads();

    if (s_last) {
        // Warp 0: compute global max M, per-split scales, total Z (64 splits, 2/lane)
        if (wid == 0) {
            const float m0 = g_pm[b * NSPLIT + lane];
            const float m1 = g_pm[b * NSPLIT + 32 + lane];
            const float z0 = g_pz[b * NSPLIT + lane];
            const float z1 = g_pz[b * NSPLIT + 32 + lane];
            float M = fmaxf(m0, m1);
            #pragma unroll
            for (int o = 16; o; o >>= 1)
                M = fmaxf(M, __shfl_xor_sync(0xFFFFFFFFu, M, o));
            const float sc0 = __expf(m0 - M);
            const float sc1 = __expf(m1 - M);
            s_scale[lane]      = sc0;
            s_scale[32 + lane] = sc1;
            float Zt = z0 * sc0 + z1 * sc1;
            #pragma unroll
            for (int o = 16; o; o >>= 1)
                Zt += __shfl_xor_sync(0xFFFFFFFFu, Zt, o);
            if (lane == 0) s_invZ = 1.f / Zt;
        }
        __syncthreads();

        const float invZ = s_invZ;
        const float* pb = g_pacc + (size_t)b * NSPLIT * DIM;
        float a = 0.f;
        #pragma unroll 8
        for (int sdx = 0; sdx < NSPLIT; sdx++)
            a += s_scale[sdx] * pb[sdx * DIM + tid];

        out[b * DIM + tid] = a * invZ;
    }
}

// ---------------------------------------------------------------------------
extern "C" void kernel_launch(void* const* d_in, const int* in_sizes, int n_in,
                              void* d_out, int out_size)
{
    const float* x     = (const float*)d_in[0];
    const float* mask  = (const float*)d_in[1];
    const float* gamma = (const float*)d_in[2];
    const float* beta  = (const float*)d_in[3];
    const float* w     = (const float*)d_in[4];
    const float* bbias = (const float*)d_in[5];
    float* out = (float*)d_out;

    ap_fused<<<BATCH * NBPB, 256>>>(x, mask, gamma, beta, w, bbias, out);
}